// round 15
// baseline (speedup 1.0000x reference)
#include <cuda_runtime.h>
#include <math.h>

#define NPROP 8192
#define NC 81
#define NFG 80
#define NDET 100
#define SCORE_T 0.05f
#define NMS_T 0.5f
#define BBOX_CLIP 4.135166556742356f   // log(1000/16)
#define CAP 384                         // max survivors/class (E[M]~235, ~10 sigma)
#define CSTRIDE 512                     // storage stride per class
#define NW64 6                          // 64-bit mask words per row
#define NW32 12                         // 32-bit words per row
#define T2 256
#define CLU 4                           // cluster size (CTAs per class)
#define FULLM 0xffffffffu

// Scratch (no cudaMalloc)
__device__ int                g_count[NFG];            // zero at load; nms resets
__device__ float4             g_cbox[NFG * CSTRIDE];   // decoded boxes (compacted)
__device__ unsigned long long g_ckey[NFG * CSTRIDE];   // score|~n keys  (compacted)

__device__ __forceinline__ void img_dims(const int* imh, const int* imw,
                                         float& W, float& H) {
    W = 1216.0f; H = 800.0f;
    if (imw) {
        int vw = *imw, vh = *imh;
        W = (vw > 0 && vw < 100000) ? (float)vw : __int_as_float(vw);
        H = (vh > 0 && vh < 100000) ? (float)vh : __int_as_float(vh);
    }
}

// ---------------------------------------------------------------------------
// Box decode (Fast R-CNN BoxCoder + clip to image)
// ---------------------------------------------------------------------------
__device__ __forceinline__ float4 decode_box(float4 p, float4 d, float W, float H) {
    float w  = p.z - p.x;
    float h  = p.w - p.y;
    float cx = p.x + 0.5f * w;
    float cy = p.y + 0.5f * h;
    float dx = d.x / 10.0f;
    float dy = d.y / 10.0f;
    float dw = fminf(d.z / 5.0f, BBOX_CLIP);
    float dh = fminf(d.w / 5.0f, BBOX_CLIP);
    float pcx = dx * w + cx;
    float pcy = dy * h + cy;
    float pw  = expf(dw) * w;
    float ph  = expf(dh) * h;
    float x1 = fminf(fmaxf(pcx - 0.5f * pw, 0.0f), W);
    float y1 = fminf(fmaxf(pcy - 0.5f * ph, 0.0f), H);
    float x2 = fminf(fmaxf(pcx + 0.5f * pw, 0.0f), W);
    float y2 = fminf(fmaxf(pcy + 0.5f * ph, 0.0f), H);
    return make_float4(x1, y1, x2, y2);
}

// ---------------------------------------------------------------------------
// Kernel 1: softmax + threshold + PUSH-TIME DECODE. 8 lanes per proposal,
// 32 proposals per block, logits staged through smem via LDG.128.
// ---------------------------------------------------------------------------
#define SM_PROPS 32
__global__ void __launch_bounds__(256, 1)
softmax_kernel(const float* __restrict__ logits,
               const float* __restrict__ proposal,
               const float* __restrict__ regs,
               const int* __restrict__ imh,
               const int* __restrict__ imw) {
    __shared__ float slog[SM_PROPS * NC];          // 10368 B
    const int tid = threadIdx.x;

    const float4* src = (const float4*)(logits + (size_t)blockIdx.x * SM_PROPS * NC);
    float4* dst = (float4*)slog;
    #pragma unroll
    for (int k = 0; k < 3; k++) {
        int idx = tid + k * 256;
        if (idx < (SM_PROPS * NC) / 4) dst[idx] = src[idx];
    }
    __syncthreads();

    const int p  = tid >> 3;
    const int l8 = tid & 7;
    const int n  = blockIdx.x * SM_PROPS + p;
    const float* row = slog + p * NC;

    float v[11];
    #pragma unroll
    for (int k = 0; k < 10; k++) v[k] = row[l8 + 8 * k];
    v[10] = (l8 == 0) ? row[80] : -INFINITY;

    float mx = v[0];
    #pragma unroll
    for (int k = 1; k < 11; k++) mx = fmaxf(mx, v[k]);
    mx = fmaxf(mx, __shfl_xor_sync(FULLM, mx, 1));
    mx = fmaxf(mx, __shfl_xor_sync(FULLM, mx, 2));
    mx = fmaxf(mx, __shfl_xor_sync(FULLM, mx, 4));

    float e[11];
    float sum = 0.0f;
    #pragma unroll
    for (int k = 0; k < 11; k++) { e[k] = expf(v[k] - mx); sum += e[k]; }
    sum += __shfl_xor_sync(FULLM, sum, 1);
    sum += __shfl_xor_sync(FULLM, sum, 2);
    sum += __shfl_xor_sync(FULLM, sum, 4);

    float W, H;
    img_dims(imh, imw, W, H);
    const float4* prop4 = (const float4*)proposal;
    const float4* reg4  = (const float4*)regs;

    bool  have = false;
    float4 pb;
    #pragma unroll
    for (int k = 0; k < 11; k++) {
        int cls = l8 + 8 * k;
        if (cls >= 1 && cls < NC) {
            float sc = e[k] / sum;
            if (sc >= SCORE_T) {
                if (!have) { pb = prop4[n]; have = true; }
                float4 d = reg4[(size_t)n * NC + cls];
                float4 b = decode_box(pb, d, W, H);
                bool keep = ((b.z - b.x) >= 1.0f) && ((b.w - b.y) >= 1.0f);
                unsigned hi = keep ? __float_as_uint(sc) : 0u;
                unsigned long long key = ((unsigned long long)hi << 32)
                    | (unsigned long long)(0xFFFFFFFFu - (unsigned)n);
                int cc = cls - 1;
                int pos = atomicAdd(&g_count[cc], 1);
                if (pos < CSTRIDE) {
                    g_cbox[cc * CSTRIDE + pos] = b;
                    g_ckey[cc * CSTRIDE + pos] = key;
                }
            }
        }
    }
}

// OR a bit into cluster-rank-0's shared mask (callable from any rank)
__device__ __forceinline__ void cluster_or32(unsigned* p, unsigned val) {
    unsigned laddr = (unsigned)__cvta_generic_to_shared(p);
    unsigned raddr;
    asm volatile("mapa.shared::cluster.u32 %0, %1, 0;" : "=r"(raddr) : "r"(laddr));
    asm volatile("red.relaxed.cluster.shared::cluster.or.b32 [%0], %1;"
                 :: "r"(raddr), "r"(val) : "memory");
}

// Plain store into cluster-rank-0's shared memory
__device__ __forceinline__ void cluster_st32(int* p, int val) {
    unsigned laddr = (unsigned)__cvta_generic_to_shared(p);
    unsigned raddr;
    asm volatile("mapa.shared::cluster.u32 %0, %1, 0;" : "=r"(raddr) : "r"(laddr));
    asm volatile("st.shared::cluster.u32 [%0], %1;"
                 :: "r"(raddr), "r"(val) : "memory");
}

// ---------------------------------------------------------------------------
// Kernel 2 (PDL secondary, 4-CTA cluster per class):
//  pre-sync: zero smem mask; post-sync: coalesced load of precomputed
//  {box,key} -> split-j rank scatter -> cluster-split pair mask (DSMEM
//  red.or) -> warp greedy scan (register rows, 4-way speculative accepts)
//  -> output. Output: boxes[8000*4] | scores[8000] | labels[8000] | valid[8000]
// ---------------------------------------------------------------------------
__global__ void __launch_bounds__(T2, 1) __cluster_dims__(CLU, 1, 1)
nms_fused(const float* __restrict__ proposal,
          const float* __restrict__ regs,
          const int* __restrict__ imh,
          const int* __restrict__ imw,
          float* __restrict__ out) {
    __shared__ float4 sbox[CAP];
    __shared__ unsigned long long skey[CAP];
    __shared__ unsigned long long smask64[CAP * NW64];   // 18 KB
    __shared__ int sidx[CAP];
    __shared__ int aidx[NDET];
    __shared__ unsigned ascr[NDET];
    __shared__ int shNa;
    __shared__ float4 shB0;
    unsigned* smask32 = (unsigned*)smask64;

    const int c   = blockIdx.x / CLU;
    const int tid = threadIdx.x;
    unsigned crank;
    asm("mov.u32 %0, %%cluster_ctarank;" : "=r"(crank));

    // -------- pre-dependency work: zero the suppression mask --------
    for (int i = tid; i < CAP * NW64; i += T2) smask64[i] = 0ull;

    // wait for softmax kernel results (no-op if launched without PDL)
    cudaGridDependencySynchronize();

    int M = g_count[c];
    if (M > CAP) M = CAP;

    float W, H;
    img_dims(imh, imw, W, H);
    const float4* prop4 = (const float4*)proposal;
    const float4* reg4  = (const float4*)regs;

    // ---- coalesced load of precomputed boxes + keys ----
    for (int i = tid; i < M; i += T2) {
        sbox[i] = g_cbox[c * CSTRIDE + i];
        skey[i] = g_ckey[c * CSTRIDE + i];
    }
    if (crank == 0 && tid == 0) shB0 = decode_box(prop4[0], reg4[c + 1], W, H);
    __syncthreads();

    // cluster sync #1: masks zeroed + tiles loaded everywhere
    asm volatile("barrier.cluster.arrive.aligned;" ::: "memory");
    asm volatile("barrier.cluster.wait.aligned;"   ::: "memory");
    if (crank == 0 && tid == 0) g_count[c] = 0;      // reset for next replay

    // ---- rank scatter, split i across cluster AND j across 4-thread groups --
    {
        int s0 = ((int)crank * M) / CLU;
        int s1 = (((int)crank + 1) * M) / CLU;
        int jc = tid & 3;
        int j0 = (jc * M) >> 2;
        int j1 = ((jc + 1) * M) >> 2;
        for (int ib = s0; ib < s1; ib += 64) {
            int i = ib + (tid >> 2);
            bool act = (i < s1);
            unsigned long long ki = act ? skey[i] : 0ull;
            int rk = 0;
            if (act) for (int j = j0; j < j1; j++) rk += (skey[j] > ki) ? 1 : 0;
            rk += __shfl_xor_sync(FULLM, rk, 1);
            rk += __shfl_xor_sync(FULLM, rk, 2);
            if (act && jc == 0) cluster_st32(&sidx[rk], i);  // keys unique
        }
    }

    // ---- triangular pair mask, split across cluster (CLU*T2 lanes) ----
    {
        long long npairs = (long long)M * (M - 1) / 2;
        const int TT = CLU * T2;                     // 1024 lanes per class
        int gt = (int)crank * T2 + tid;
        long long p0 = npairs * gt / TT;
        long long p1 = npairs * (gt + 1) / TT;
        if (p0 < p1) {
            int j = (int)((1.0f + sqrtf((float)(8.0 * (double)p0 + 1.0))) * 0.5f);
            while ((long long)j * (j - 1) / 2 > p0) j--;
            while ((long long)(j + 1) * j / 2 <= p0) j++;
            int i = (int)(p0 - (long long)j * (j - 1) / 2);

            unsigned long long kj = skey[j];
            float4 bj = sbox[j];
            float  aj = (bj.z - bj.x) * (bj.w - bj.y);
            for (long long p = p0; p < p1; p++) {
                unsigned long long ki = skey[i];
                float4 bi = sbox[i];
                float  ai = (bi.z - bi.x) * (bi.w - bi.y);
                float lx = fmaxf(bi.x, bj.x);
                float ly = fmaxf(bi.y, bj.y);
                float rx = fminf(bi.z, bj.z);
                float ry = fminf(bi.w, bj.w);
                float iw = fmaxf(rx - lx, 0.0f);
                float ih = fmaxf(ry - ly, 0.0f);
                float inter = iw * ih;
                float iou = inter / (ai + aj - inter + 1e-12f);
                if (iou > NMS_T) {
                    int loser  = (kj > ki) ? i : j;
                    int winner = (kj > ki) ? j : i;
                    cluster_or32(&smask32[loser * NW32 + (winner >> 5)],
                                 1u << (winner & 31));
                }
                if (++i == j) {
                    i = 0; j++;
                    kj = skey[j]; bj = sbox[j];
                    aj = (bj.z - bj.x) * (bj.w - bj.y);
                }
            }
        }
    }

    // cluster sync #2: all sidx stores + mask bits landed in rank 0
    asm volatile("barrier.cluster.arrive.aligned;" ::: "memory");
    asm volatile("barrier.cluster.wait.aligned;"   ::: "memory");
    if (crank != 0) return;

    // ---- warp greedy scan: register rows + 4-way speculative accepts ----
    if (tid < 32) {
        const int lane = tid;
        unsigned long long a0 = 0, a1 = 0, a2 = 0, a3 = 0, a4 = 0, a5 = 0;
        int na = 0;
        for (int chunk = 0; chunk * 32 < M && na < NDET; chunk++) {
            int r = chunk * 32 + lane;
            bool haveR = (r < M);
            int i = haveR ? sidx[r] : 0;
            unsigned sc = haveR ? (unsigned)(skey[i] >> 32) : 0u;
            bool alive = (sc != 0u);
            unsigned long long r0 = 0, r1 = 0, r2 = 0, r3 = 0, r4 = 0, r5 = 0;
            if (haveR) {
                const unsigned long long* row = &smask64[i * NW64];
                r0 = row[0]; r1 = row[1]; r2 = row[2];
                r3 = row[3]; r4 = row[4]; r5 = row[5];
            }
            unsigned long long sup = (r0 & a0) | (r1 & a1) | (r2 & a2)
                                   | (r3 & a3) | (r4 & a4) | (r5 & a5);
            unsigned pend   = __ballot_sync(FULLM, alive && (sup == 0ull));
            unsigned aliveb = __ballot_sync(FULLM, alive);

            #define OWNBIT(bb, ii) do {                                        \
                int _w = (ii) >> 6;                                            \
                unsigned long long _s = (_w == 0) ? r0 : (_w == 1) ? r1        \
                                      : (_w == 2) ? r2 : (_w == 3) ? r3        \
                                      : (_w == 4) ? r4 : r5;                   \
                bb = ((_s >> ((ii) & 63)) & 1ull) != 0ull; } while (0)
            #define ABIT(ii) do {                                              \
                int _w = (ii) >> 6;                                            \
                unsigned long long _b = 1ull << ((ii) & 63);                   \
                a0 |= (_w == 0) ? _b : 0ull; a1 |= (_w == 1) ? _b : 0ull;      \
                a2 |= (_w == 2) ? _b : 0ull; a3 |= (_w == 3) ? _b : 0ull;      \
                a4 |= (_w == 4) ? _b : 0ull; a5 |= (_w == 5) ? _b : 0ull; } while (0)

            while (pend && na < NDET) {
                int l1 = __ffs(pend) - 1;
                unsigned rem1 = pend & (pend - 1);
                int l2 = rem1 ? (__ffs(rem1) - 1) : -1;
                unsigned rem2 = rem1 & (rem1 - 1);
                int l3 = rem2 ? (__ffs(rem2) - 1) : -1;
                unsigned rem3 = rem2 & (rem2 - 1);
                int l4 = rem3 ? (__ffs(rem3) - 1) : -1;

                int i1 = __shfl_sync(FULLM, i, l1);
                int i2 = __shfl_sync(FULLM, i, (l2 >= 0) ? l2 : l1);
                int i3 = __shfl_sync(FULLM, i, (l3 >= 0) ? l3 : l1);
                int i4 = __shfl_sync(FULLM, i, (l4 >= 0) ? l4 : l1);

                bool b1, b2, b3, b4;
                OWNBIT(b1, i1); OWNBIT(b2, i2); OWNBIT(b3, i3); OWNBIT(b4, i4);
                unsigned s1 = __ballot_sync(FULLM, b1);
                unsigned s2 = __ballot_sync(FULLM, b2);
                unsigned s3 = __ballot_sync(FULLM, b3);
                unsigned s4 = __ballot_sync(FULLM, b4);

                if (lane == l1) { aidx[na] = i; ascr[na] = sc; }
                na++; ABIT(i1);
                if (na == NDET) break;

                bool ok2 = (l2 >= 0) && !((s1 >> (l2 & 31)) & 1u);
                if (ok2) { if (lane == l2) { aidx[na] = i; ascr[na] = sc; }
                           na++; ABIT(i2); }
                if (na == NDET) break;

                bool sup3 = ((s1 >> (l3 & 31)) & 1u)
                          || (ok2 && ((s2 >> (l3 & 31)) & 1u));
                bool ok3 = (l3 >= 0) && !sup3;
                if (ok3) { if (lane == l3) { aidx[na] = i; ascr[na] = sc; }
                           na++; ABIT(i3); }
                if (na == NDET) break;

                bool sup4 = ((s1 >> (l4 & 31)) & 1u)
                          || (ok2 && ((s2 >> (l4 & 31)) & 1u))
                          || (ok3 && ((s3 >> (l4 & 31)) & 1u));
                bool ok4 = (l4 >= 0) && !sup4;
                if (ok4) { if (lane == l4) { aidx[na] = i; ascr[na] = sc; }
                           na++; ABIT(i4); }

                pend &= ~(1u << l1);
                if (l2 >= 0) pend &= ~(1u << l2);
                if (l3 >= 0) pend &= ~(1u << l3);
                if (l4 >= 0) pend &= ~(1u << l4);
                pend &= ~s1;
                if (ok2) pend &= ~s2;
                if (ok3) pend &= ~s3;
                if (ok4) pend &= ~s4;
            }
            #undef OWNBIT
            #undef ABIT
            if (na == NDET || aliveb != FULLM) break;  // done / later ranks dead
        }
        if (lane == 0) shNa = na;
    }
    __syncthreads();

    // ---- parallel output ----
    const int obase = c * NDET * 4;
    const int sbase = NFG * NDET * 4;        // 32000
    const int lbase = sbase + NFG * NDET;    // 40000
    const int vbase = lbase + NFG * NDET;    // 48000
    const float label = (float)(c + 1);
    const int na = shNa;

    for (int a = tid; a < na; a += T2) {
        float4 b = sbox[aidx[a]];
        out[obase + a * 4 + 0] = b.x;
        out[obase + a * 4 + 1] = b.y;
        out[obase + a * 4 + 2] = b.z;
        out[obase + a * 4 + 3] = b.w;
        int slot = c * NDET + a;
        out[sbase + slot] = __uint_as_float(ascr[a]);
        out[lbase + slot] = label;
        out[vbase + slot] = 1.0f;
    }
    const float4 b0 = shB0;
    for (int jt = na + tid; jt < NDET; jt += T2) {
        out[obase + jt * 4 + 0] = b0.x;
        out[obase + jt * 4 + 1] = b0.y;
        out[obase + jt * 4 + 2] = b0.z;
        out[obase + jt * 4 + 3] = b0.w;
        int slot = c * NDET + jt;
        out[sbase + slot] = 0.0f;
        out[lbase + slot] = label;
        out[vbase + slot] = 0.0f;
    }
}

extern "C" void kernel_launch(void* const* d_in, const int* in_sizes, int n_in,
                              void* d_out, int out_size) {
    const float* proposal = (const float*)d_in[0];
    const float* logits   = (const float*)d_in[1];
    const float* regs     = (const float*)d_in[2];
    const int*   imh      = (n_in >= 5) ? (const int*)d_in[3] : nullptr;
    const int*   imw      = (n_in >= 5) ? (const int*)d_in[4] : nullptr;
    float* outf = (float*)d_out;

    softmax_kernel<<<NPROP / SM_PROPS, 256>>>(logits, proposal, regs, imh, imw);

    // PDL launch: nms ramps up while softmax still runs.
    cudaLaunchConfig_t cfg = {};
    cfg.gridDim  = dim3(NFG * CLU, 1, 1);
    cfg.blockDim = dim3(T2, 1, 1);
    cudaLaunchAttribute attrs[1];
    attrs[0].id = cudaLaunchAttributeProgrammaticStreamSerialization;
    attrs[0].val.programmaticStreamSerializationAllowed = 1;
    cfg.attrs = attrs;
    cfg.numAttrs = 1;
    cudaError_t err = cudaLaunchKernelEx(&cfg, nms_fused,
                                         proposal, regs, imh, imw, outf);
    if (err != cudaSuccess) {
        nms_fused<<<NFG * CLU, T2>>>(proposal, regs, imh, imw, outf);
    }
}

// round 16
// speedup vs baseline: 1.0063x; 1.0063x over previous
#include <cuda_runtime.h>
#include <math.h>

#define NPROP 8192
#define NC 81
#define NFG 80
#define NDET 100
#define SCORE_T 0.05f
#define NMS_T 0.5f
#define BBOX_CLIP 4.135166556742356f   // log(1000/16)
#define CAP 384                         // max survivors/class (E[M]~235, ~10 sigma)
#define CSTRIDE 512                     // storage stride per class
#define NW64 6                          // 64-bit mask words per row
#define NW32 12                         // 32-bit words per row
#define T2 256
#define CLU 4                           // cluster size (CTAs per class)
#define FULLM 0xffffffffu

// Scratch (no cudaMalloc)
__device__ int                g_count[NFG];            // zero at load; nms resets
__device__ float4             g_cbox[NFG * CSTRIDE];   // decoded boxes (compacted)
__device__ unsigned long long g_ckey[NFG * CSTRIDE];   // score|~n keys  (compacted)

__device__ __forceinline__ void img_dims(const int* imh, const int* imw,
                                         float& W, float& H) {
    W = 1216.0f; H = 800.0f;
    if (imw) {
        int vw = *imw, vh = *imh;
        W = (vw > 0 && vw < 100000) ? (float)vw : __int_as_float(vw);
        H = (vh > 0 && vh < 100000) ? (float)vh : __int_as_float(vh);
    }
}

// ---------------------------------------------------------------------------
// Box decode (Fast R-CNN BoxCoder + clip to image)
// ---------------------------------------------------------------------------
__device__ __forceinline__ float4 decode_box(float4 p, float4 d, float W, float H) {
    float w  = p.z - p.x;
    float h  = p.w - p.y;
    float cx = p.x + 0.5f * w;
    float cy = p.y + 0.5f * h;
    float dx = d.x / 10.0f;
    float dy = d.y / 10.0f;
    float dw = fminf(d.z / 5.0f, BBOX_CLIP);
    float dh = fminf(d.w / 5.0f, BBOX_CLIP);
    float pcx = dx * w + cx;
    float pcy = dy * h + cy;
    float pw  = expf(dw) * w;
    float ph  = expf(dh) * h;
    float x1 = fminf(fmaxf(pcx - 0.5f * pw, 0.0f), W);
    float y1 = fminf(fmaxf(pcy - 0.5f * ph, 0.0f), H);
    float x2 = fminf(fmaxf(pcx + 0.5f * pw, 0.0f), W);
    float y2 = fminf(fmaxf(pcy + 0.5f * ph, 0.0f), H);
    return make_float4(x1, y1, x2, y2);
}

// ---------------------------------------------------------------------------
// Kernel 1: softmax + threshold + push-time decode.
// 16 proposals per 128-thread block (8 lanes/proposal) -> 512 blocks for MLP.
// ---------------------------------------------------------------------------
#define SM_PROPS 16
#define T1 128
__global__ void __launch_bounds__(T1, 1)
softmax_kernel(const float* __restrict__ logits,
               const float* __restrict__ proposal,
               const float* __restrict__ regs,
               const int* __restrict__ imh,
               const int* __restrict__ imw) {
    __shared__ float slog[SM_PROPS * NC];          // 1296 floats = 5184 B
    const int tid = threadIdx.x;

    const float4* src = (const float4*)(logits + (size_t)blockIdx.x * SM_PROPS * NC);
    float4* dst = (float4*)slog;
    #pragma unroll
    for (int k = 0; k < 3; k++) {
        int idx = tid + k * T1;
        if (idx < (SM_PROPS * NC) / 4) dst[idx] = src[idx];
    }
    __syncthreads();

    const int p  = tid >> 3;
    const int l8 = tid & 7;
    const int n  = blockIdx.x * SM_PROPS + p;
    const float* row = slog + p * NC;

    float v[11];
    #pragma unroll
    for (int k = 0; k < 10; k++) v[k] = row[l8 + 8 * k];
    v[10] = (l8 == 0) ? row[80] : -INFINITY;

    float mx = v[0];
    #pragma unroll
    for (int k = 1; k < 11; k++) mx = fmaxf(mx, v[k]);
    mx = fmaxf(mx, __shfl_xor_sync(FULLM, mx, 1));
    mx = fmaxf(mx, __shfl_xor_sync(FULLM, mx, 2));
    mx = fmaxf(mx, __shfl_xor_sync(FULLM, mx, 4));

    float e[11];
    float sum = 0.0f;
    #pragma unroll
    for (int k = 0; k < 11; k++) { e[k] = expf(v[k] - mx); sum += e[k]; }
    sum += __shfl_xor_sync(FULLM, sum, 1);
    sum += __shfl_xor_sync(FULLM, sum, 2);
    sum += __shfl_xor_sync(FULLM, sum, 4);

    float W, H;
    img_dims(imh, imw, W, H);
    const float4* prop4 = (const float4*)proposal;
    const float4* reg4  = (const float4*)regs;

    // any-pass predicate first -> unconditional proposal load (breaks the
    // dependent-branch chain on the common path)
    float sc[11];
    bool any = false;
    #pragma unroll
    for (int k = 0; k < 11; k++) {
        int cls = l8 + 8 * k;
        sc[k] = e[k] / sum;
        if (cls >= 1 && cls < NC && sc[k] >= SCORE_T) any = true;
    }
    if (any) {
        float4 pb = prop4[n];
        #pragma unroll
        for (int k = 0; k < 11; k++) {
            int cls = l8 + 8 * k;
            if (cls >= 1 && cls < NC && sc[k] >= SCORE_T) {
                float4 d = reg4[(size_t)n * NC + cls];
                float4 b = decode_box(pb, d, W, H);
                bool keep = ((b.z - b.x) >= 1.0f) && ((b.w - b.y) >= 1.0f);
                unsigned hi = keep ? __float_as_uint(sc[k]) : 0u;
                unsigned long long key = ((unsigned long long)hi << 32)
                    | (unsigned long long)(0xFFFFFFFFu - (unsigned)n);
                int cc = cls - 1;
                int pos = atomicAdd(&g_count[cc], 1);
                if (pos < CSTRIDE) {
                    g_cbox[cc * CSTRIDE + pos] = b;
                    g_ckey[cc * CSTRIDE + pos] = key;
                }
            }
        }
    }
}

// OR a bit into cluster-rank-0's shared mask (callable from any rank)
__device__ __forceinline__ void cluster_or32(unsigned* p, unsigned val) {
    unsigned laddr = (unsigned)__cvta_generic_to_shared(p);
    unsigned raddr;
    asm volatile("mapa.shared::cluster.u32 %0, %1, 0;" : "=r"(raddr) : "r"(laddr));
    asm volatile("red.relaxed.cluster.shared::cluster.or.b32 [%0], %1;"
                 :: "r"(raddr), "r"(val) : "memory");
}

// Plain store into cluster-rank-0's shared memory
__device__ __forceinline__ void cluster_st32(int* p, int val) {
    unsigned laddr = (unsigned)__cvta_generic_to_shared(p);
    unsigned raddr;
    asm volatile("mapa.shared::cluster.u32 %0, %1, 0;" : "=r"(raddr) : "r"(laddr));
    asm volatile("st.shared::cluster.u32 [%0], %1;"
                 :: "r"(raddr), "r"(val) : "memory");
}

// ---------------------------------------------------------------------------
// Kernel 2 (PDL secondary, 4-CTA cluster per class): unchanged from R15.
// Output (float32): boxes[8000*4] | scores[8000] | labels[8000] | valid[8000]
// ---------------------------------------------------------------------------
__global__ void __launch_bounds__(T2, 1) __cluster_dims__(CLU, 1, 1)
nms_fused(const float* __restrict__ proposal,
          const float* __restrict__ regs,
          const int* __restrict__ imh,
          const int* __restrict__ imw,
          float* __restrict__ out) {
    __shared__ float4 sbox[CAP];
    __shared__ unsigned long long skey[CAP];
    __shared__ unsigned long long smask64[CAP * NW64];   // 18 KB
    __shared__ int sidx[CAP];
    __shared__ int aidx[NDET];
    __shared__ unsigned ascr[NDET];
    __shared__ int shNa;
    __shared__ float4 shB0;
    unsigned* smask32 = (unsigned*)smask64;

    const int c   = blockIdx.x / CLU;
    const int tid = threadIdx.x;
    unsigned crank;
    asm("mov.u32 %0, %%cluster_ctarank;" : "=r"(crank));

    // -------- pre-dependency work: zero the suppression mask --------
    for (int i = tid; i < CAP * NW64; i += T2) smask64[i] = 0ull;

    // wait for softmax kernel results (no-op if launched without PDL)
    cudaGridDependencySynchronize();

    int M = g_count[c];
    if (M > CAP) M = CAP;

    float W, H;
    img_dims(imh, imw, W, H);
    const float4* prop4 = (const float4*)proposal;
    const float4* reg4  = (const float4*)regs;

    // ---- coalesced load of precomputed boxes + keys ----
    for (int i = tid; i < M; i += T2) {
        sbox[i] = g_cbox[c * CSTRIDE + i];
        skey[i] = g_ckey[c * CSTRIDE + i];
    }
    if (crank == 0 && tid == 0) shB0 = decode_box(prop4[0], reg4[c + 1], W, H);
    __syncthreads();

    // cluster sync #1: masks zeroed + tiles loaded everywhere
    asm volatile("barrier.cluster.arrive.aligned;" ::: "memory");
    asm volatile("barrier.cluster.wait.aligned;"   ::: "memory");
    if (crank == 0 && tid == 0) g_count[c] = 0;      // reset for next replay

    // ---- rank scatter, split i across cluster AND j across 4-thread groups --
    {
        int s0 = ((int)crank * M) / CLU;
        int s1 = (((int)crank + 1) * M) / CLU;
        int jc = tid & 3;
        int j0 = (jc * M) >> 2;
        int j1 = ((jc + 1) * M) >> 2;
        for (int ib = s0; ib < s1; ib += 64) {
            int i = ib + (tid >> 2);
            bool act = (i < s1);
            unsigned long long ki = act ? skey[i] : 0ull;
            int rk = 0;
            if (act) for (int j = j0; j < j1; j++) rk += (skey[j] > ki) ? 1 : 0;
            rk += __shfl_xor_sync(FULLM, rk, 1);
            rk += __shfl_xor_sync(FULLM, rk, 2);
            if (act && jc == 0) cluster_st32(&sidx[rk], i);  // keys unique
        }
    }

    // ---- triangular pair mask, split across cluster (CLU*T2 lanes) ----
    {
        long long npairs = (long long)M * (M - 1) / 2;
        const int TT = CLU * T2;                     // 1024 lanes per class
        int gt = (int)crank * T2 + tid;
        long long p0 = npairs * gt / TT;
        long long p1 = npairs * (gt + 1) / TT;
        if (p0 < p1) {
            int j = (int)((1.0f + sqrtf((float)(8.0 * (double)p0 + 1.0))) * 0.5f);
            while ((long long)j * (j - 1) / 2 > p0) j--;
            while ((long long)(j + 1) * j / 2 <= p0) j++;
            int i = (int)(p0 - (long long)j * (j - 1) / 2);

            unsigned long long kj = skey[j];
            float4 bj = sbox[j];
            float  aj = (bj.z - bj.x) * (bj.w - bj.y);
            for (long long p = p0; p < p1; p++) {
                unsigned long long ki = skey[i];
                float4 bi = sbox[i];
                float  ai = (bi.z - bi.x) * (bi.w - bi.y);
                float lx = fmaxf(bi.x, bj.x);
                float ly = fmaxf(bi.y, bj.y);
                float rx = fminf(bi.z, bj.z);
                float ry = fminf(bi.w, bj.w);
                float iw = fmaxf(rx - lx, 0.0f);
                float ih = fmaxf(ry - ly, 0.0f);
                float inter = iw * ih;
                float iou = inter / (ai + aj - inter + 1e-12f);
                if (iou > NMS_T) {
                    int loser  = (kj > ki) ? i : j;
                    int winner = (kj > ki) ? j : i;
                    cluster_or32(&smask32[loser * NW32 + (winner >> 5)],
                                 1u << (winner & 31));
                }
                if (++i == j) {
                    i = 0; j++;
                    kj = skey[j]; bj = sbox[j];
                    aj = (bj.z - bj.x) * (bj.w - bj.y);
                }
            }
        }
    }

    // cluster sync #2: all sidx stores + mask bits landed in rank 0
    asm volatile("barrier.cluster.arrive.aligned;" ::: "memory");
    asm volatile("barrier.cluster.wait.aligned;"   ::: "memory");
    if (crank != 0) return;

    // ---- warp greedy scan: register rows + 4-way speculative accepts ----
    if (tid < 32) {
        const int lane = tid;
        unsigned long long a0 = 0, a1 = 0, a2 = 0, a3 = 0, a4 = 0, a5 = 0;
        int na = 0;
        for (int chunk = 0; chunk * 32 < M && na < NDET; chunk++) {
            int r = chunk * 32 + lane;
            bool haveR = (r < M);
            int i = haveR ? sidx[r] : 0;
            unsigned sc = haveR ? (unsigned)(skey[i] >> 32) : 0u;
            bool alive = (sc != 0u);
            unsigned long long r0 = 0, r1 = 0, r2 = 0, r3 = 0, r4 = 0, r5 = 0;
            if (haveR) {
                const unsigned long long* row = &smask64[i * NW64];
                r0 = row[0]; r1 = row[1]; r2 = row[2];
                r3 = row[3]; r4 = row[4]; r5 = row[5];
            }
            unsigned long long sup = (r0 & a0) | (r1 & a1) | (r2 & a2)
                                   | (r3 & a3) | (r4 & a4) | (r5 & a5);
            unsigned pend   = __ballot_sync(FULLM, alive && (sup == 0ull));
            unsigned aliveb = __ballot_sync(FULLM, alive);

            #define OWNBIT(bb, ii) do {                                        \
                int _w = (ii) >> 6;                                            \
                unsigned long long _s = (_w == 0) ? r0 : (_w == 1) ? r1        \
                                      : (_w == 2) ? r2 : (_w == 3) ? r3        \
                                      : (_w == 4) ? r4 : r5;                   \
                bb = ((_s >> ((ii) & 63)) & 1ull) != 0ull; } while (0)
            #define ABIT(ii) do {                                              \
                int _w = (ii) >> 6;                                            \
                unsigned long long _b = 1ull << ((ii) & 63);                   \
                a0 |= (_w == 0) ? _b : 0ull; a1 |= (_w == 1) ? _b : 0ull;      \
                a2 |= (_w == 2) ? _b : 0ull; a3 |= (_w == 3) ? _b : 0ull;      \
                a4 |= (_w == 4) ? _b : 0ull; a5 |= (_w == 5) ? _b : 0ull; } while (0)

            while (pend && na < NDET) {
                int l1 = __ffs(pend) - 1;
                unsigned rem1 = pend & (pend - 1);
                int l2 = rem1 ? (__ffs(rem1) - 1) : -1;
                unsigned rem2 = rem1 & (rem1 - 1);
                int l3 = rem2 ? (__ffs(rem2) - 1) : -1;
                unsigned rem3 = rem2 & (rem2 - 1);
                int l4 = rem3 ? (__ffs(rem3) - 1) : -1;

                int i1 = __shfl_sync(FULLM, i, l1);
                int i2 = __shfl_sync(FULLM, i, (l2 >= 0) ? l2 : l1);
                int i3 = __shfl_sync(FULLM, i, (l3 >= 0) ? l3 : l1);
                int i4 = __shfl_sync(FULLM, i, (l4 >= 0) ? l4 : l1);

                bool b1, b2, b3, b4;
                OWNBIT(b1, i1); OWNBIT(b2, i2); OWNBIT(b3, i3); OWNBIT(b4, i4);
                unsigned s1 = __ballot_sync(FULLM, b1);
                unsigned s2 = __ballot_sync(FULLM, b2);
                unsigned s3 = __ballot_sync(FULLM, b3);
                unsigned s4 = __ballot_sync(FULLM, b4);

                if (lane == l1) { aidx[na] = i; ascr[na] = sc; }
                na++; ABIT(i1);
                if (na == NDET) break;

                bool ok2 = (l2 >= 0) && !((s1 >> (l2 & 31)) & 1u);
                if (ok2) { if (lane == l2) { aidx[na] = i; ascr[na] = sc; }
                           na++; ABIT(i2); }
                if (na == NDET) break;

                bool sup3 = ((s1 >> (l3 & 31)) & 1u)
                          || (ok2 && ((s2 >> (l3 & 31)) & 1u));
                bool ok3 = (l3 >= 0) && !sup3;
                if (ok3) { if (lane == l3) { aidx[na] = i; ascr[na] = sc; }
                           na++; ABIT(i3); }
                if (na == NDET) break;

                bool sup4 = ((s1 >> (l4 & 31)) & 1u)
                          || (ok2 && ((s2 >> (l4 & 31)) & 1u))
                          || (ok3 && ((s3 >> (l4 & 31)) & 1u));
                bool ok4 = (l4 >= 0) && !sup4;
                if (ok4) { if (lane == l4) { aidx[na] = i; ascr[na] = sc; }
                           na++; ABIT(i4); }

                pend &= ~(1u << l1);
                if (l2 >= 0) pend &= ~(1u << l2);
                if (l3 >= 0) pend &= ~(1u << l3);
                if (l4 >= 0) pend &= ~(1u << l4);
                pend &= ~s1;
                if (ok2) pend &= ~s2;
                if (ok3) pend &= ~s3;
                if (ok4) pend &= ~s4;
            }
            #undef OWNBIT
            #undef ABIT
            if (na == NDET || aliveb != FULLM) break;  // done / later ranks dead
        }
        if (lane == 0) shNa = na;
    }
    __syncthreads();

    // ---- parallel output ----
    const int obase = c * NDET * 4;
    const int sbase = NFG * NDET * 4;        // 32000
    const int lbase = sbase + NFG * NDET;    // 40000
    const int vbase = lbase + NFG * NDET;    // 48000
    const float label = (float)(c + 1);
    const int na = shNa;

    for (int a = tid; a < na; a += T2) {
        float4 b = sbox[aidx[a]];
        out[obase + a * 4 + 0] = b.x;
        out[obase + a * 4 + 1] = b.y;
        out[obase + a * 4 + 2] = b.z;
        out[obase + a * 4 + 3] = b.w;
        int slot = c * NDET + a;
        out[sbase + slot] = __uint_as_float(ascr[a]);
        out[lbase + slot] = label;
        out[vbase + slot] = 1.0f;
    }
    const float4 b0 = shB0;
    for (int jt = na + tid; jt < NDET; jt += T2) {
        out[obase + jt * 4 + 0] = b0.x;
        out[obase + jt * 4 + 1] = b0.y;
        out[obase + jt * 4 + 2] = b0.z;
        out[obase + jt * 4 + 3] = b0.w;
        int slot = c * NDET + jt;
        out[sbase + slot] = 0.0f;
        out[lbase + slot] = label;
        out[vbase + slot] = 0.0f;
    }
}

extern "C" void kernel_launch(void* const* d_in, const int* in_sizes, int n_in,
                              void* d_out, int out_size) {
    const float* proposal = (const float*)d_in[0];
    const float* logits   = (const float*)d_in[1];
    const float* regs     = (const float*)d_in[2];
    const int*   imh      = (n_in >= 5) ? (const int*)d_in[3] : nullptr;
    const int*   imw      = (n_in >= 5) ? (const int*)d_in[4] : nullptr;
    float* outf = (float*)d_out;

    softmax_kernel<<<NPROP / SM_PROPS, T1>>>(logits, proposal, regs, imh, imw);

    // PDL launch: nms ramps up while softmax still runs.
    cudaLaunchConfig_t cfg = {};
    cfg.gridDim  = dim3(NFG * CLU, 1, 1);
    cfg.blockDim = dim3(T2, 1, 1);
    cudaLaunchAttribute attrs[1];
    attrs[0].id = cudaLaunchAttributeProgrammaticStreamSerialization;
    attrs[0].val.programmaticStreamSerializationAllowed = 1;
    cfg.attrs = attrs;
    cfg.numAttrs = 1;
    cudaError_t err = cudaLaunchKernelEx(&cfg, nms_fused,
                                         proposal, regs, imh, imw, outf);
    if (err != cudaSuccess) {
        nms_fused<<<NFG * CLU, T2>>>(proposal, regs, imh, imw, outf);
    }
}